// round 10
// baseline (speedup 1.0000x reference)
#include <cuda_runtime.h>
#include <cstdint>

#define NN 100000
#define EE 1600000
#define HID 64

// ---------------- device scratch (no runtime allocation allowed) ------------
__device__ float g_B0[NN * HID];
__device__ float g_B1[NN * HID];
__device__ float g_B2[NN * HID];
__device__ float g_dinv[NN];
__device__ float g_deg[NN];
__device__ float g_z2[(size_t)EE * (HID / 2)];
__device__ double g_s1[HID], g_q1[HID];
__device__ double g_s2[HID / 2], g_q2[HID / 2];
__device__ float g_W2f[HID * (HID / 2)];
__device__ float g_b2f[HID / 2];
__device__ float g_W3f[(HID / 2) * 2];
__device__ float g_b3f[2];

// ---------------- degree + stats init ---------------------------------------
__global__ void deg_init_kernel(int n) {
    int v = blockIdx.x * 256 + threadIdx.x;
    if (v < n) g_deg[v] = 1.0f;  // self-loop
    if (blockIdx.x == 0) {
        int t = threadIdx.x;
        if (t < HID) { g_s1[t] = 0.0; g_q1[t] = 0.0; }
        if (t < HID / 2) { g_s2[t] = 0.0; g_q2[t] = 0.0; }
    }
}

__global__ void deg_count_kernel(const int* __restrict__ ei, int E) {
    int e = blockIdx.x * 256 + threadIdx.x;
    if (e < E) atomicAdd(&g_deg[ei[(size_t)E + e]], 1.0f);
}

__global__ void deg_finish_kernel(int n) {
    int v = blockIdx.x * 256 + threadIdx.x;
    if (v < n) g_dinv[v] = rsqrtf(g_deg[v]);
}

// ---------------- layer-1 GEMM (K=3) + fused self-init ----------------------
// C = x@W1 ; O = b1 + C*dinv^2   (O is the scatter accumulator base)
__global__ __launch_bounds__(256) void gemm_k3_kernel(
    const float* __restrict__ X, const float* __restrict__ W,
    const float* __restrict__ bias,
    float* __restrict__ C, float* __restrict__ O, int n)
{
    __shared__ float Ws[3 * 64];
    int tid = threadIdx.x;
    if (tid < 192) Ws[tid] = W[tid];
    __syncthreads();
    int idx = blockIdx.x * 256 + tid;
    int v = idx >> 4;
    int c4 = (idx & 15) * 4;
    if (v >= n) return;
    float x0 = X[v * 3 + 0], x1 = X[v * 3 + 1], x2 = X[v * 3 + 2];
    float4 w0 = *(const float4*)&Ws[0 * 64 + c4];
    float4 w1 = *(const float4*)&Ws[1 * 64 + c4];
    float4 w2 = *(const float4*)&Ws[2 * 64 + c4];
    float4 o;
    o.x = x0 * w0.x + x1 * w1.x + x2 * w2.x;
    o.y = x0 * w0.y + x1 * w1.y + x2 * w2.y;
    o.z = x0 * w0.z + x1 * w1.z + x2 * w2.z;
    o.w = x0 * w0.w + x1 * w1.w + x2 * w2.w;
    *(float4*)&C[v * 64 + c4] = o;
    float dv = g_dinv[v];
    float sw = dv * dv;
    float4 b4 = *(const float4*)&bias[c4];
    float4 s;
    s.x = b4.x + o.x * sw; s.y = b4.y + o.y * sw;
    s.z = b4.z + o.z * sw; s.w = b4.w + o.w * sw;
    *(float4*)&O[(size_t)v * 64 + c4] = s;
}

// ---------------- 64x64 tiled GEMM + optional fused self-init ---------------
// C = [relu](A) @ W ; if O != null:  O = bias_self + C*dinv^2
__global__ __launch_bounds__(256) void gemm64_kernel(
    const float* __restrict__ A, const float* __restrict__ W,
    float* __restrict__ C, const float* __restrict__ bias_self,
    float* __restrict__ O, int n, int relu_in)
{
    __shared__ float As[64 * 68];
    __shared__ float Ws[64 * 64];
    int tid = threadIdx.x;
    int rowbase = blockIdx.x * 64;

    for (int i = tid; i < 1024; i += 256)
        ((float4*)Ws)[i] = ((const float4*)W)[i];

    for (int i = tid; i < 1024; i += 256) {
        int r = i >> 4;
        int c4 = (i & 15) * 4;
        float4 v;
        if (rowbase + r < n) v = *(const float4*)&A[(size_t)(rowbase + r) * 64 + c4];
        else v = make_float4(0.f, 0.f, 0.f, 0.f);
        if (relu_in) {
            v.x = fmaxf(v.x, 0.f); v.y = fmaxf(v.y, 0.f);
            v.z = fmaxf(v.z, 0.f); v.w = fmaxf(v.w, 0.f);
        }
        *(float4*)&As[r * 68 + c4] = v;
    }
    __syncthreads();

    int rg = (tid >> 4) * 4;
    int cg = (tid & 15) * 4;
    float4 acc0 = make_float4(0, 0, 0, 0), acc1 = acc0, acc2 = acc0, acc3 = acc0;
#pragma unroll
    for (int k = 0; k < 64; k++) {
        float4 wv = *(const float4*)&Ws[k * 64 + cg];
        float a0 = As[(rg + 0) * 68 + k];
        float a1 = As[(rg + 1) * 68 + k];
        float a2 = As[(rg + 2) * 68 + k];
        float a3 = As[(rg + 3) * 68 + k];
        acc0.x += a0 * wv.x; acc0.y += a0 * wv.y; acc0.z += a0 * wv.z; acc0.w += a0 * wv.w;
        acc1.x += a1 * wv.x; acc1.y += a1 * wv.y; acc1.z += a1 * wv.z; acc1.w += a1 * wv.w;
        acc2.x += a2 * wv.x; acc2.y += a2 * wv.y; acc2.z += a2 * wv.z; acc2.w += a2 * wv.w;
        acc3.x += a3 * wv.x; acc3.y += a3 * wv.y; acc3.z += a3 * wv.z; acc3.w += a3 * wv.w;
    }
    float4 accs[4] = {acc0, acc1, acc2, acc3};
#pragma unroll
    for (int rr = 0; rr < 4; rr++) {
        int row = rowbase + rg + rr;
        if (row < n) {
            *(float4*)&C[(size_t)row * 64 + cg] = accs[rr];
            if (O) {
                float dv = g_dinv[row];
                float sw = dv * dv;
                float4 b4 = *(const float4*)&bias_self[cg];
                float4 s;
                s.x = b4.x + accs[rr].x * sw; s.y = b4.y + accs[rr].y * sw;
                s.z = b4.z + accs[rr].z * sw; s.w = b4.w + accs[rr].w * sw;
                *(float4*)&O[(size_t)row * 64 + cg] = s;
            }
        }
    }
}

// ---------------- edge scatter: O[col] += T[row] * dinv[row]*dinv[col] -------
__global__ __launch_bounds__(256) void scatter_kernel(
    const int* __restrict__ ei, const float* __restrict__ T,
    float* __restrict__ O, int E)
{
    long long idx = (long long)blockIdx.x * 256 + threadIdx.x;
    int e = (int)(idx >> 4);
    int part = ((int)idx & 15) * 4;
    if (e >= E) return;
    int r = ei[e];
    int c = ei[(size_t)E + e];
    float w = g_dinv[r] * g_dinv[c];
    float4 v = *(const float4*)&T[(size_t)r * 64 + part];
    v.x *= w; v.y *= w; v.z *= w; v.w *= w;
    float* p = &O[(size_t)c * 64 + part];
    asm volatile("red.global.add.v4.f32 [%0], {%1,%2,%3,%4};"
                 :: "l"(p), "f"(v.x), "f"(v.y), "f"(v.z), "f"(v.w) : "memory");
}

// ---------------- edge pass 1: BN1 statistics of z1 -------------------------
__global__ __launch_bounds__(256) void edge_pass1_kernel(
    const int* __restrict__ ei, const float* __restrict__ A,
    const float* __restrict__ B, const float* __restrict__ bm1, int E)
{
    int lane = threadIdx.x & 31;
    int wid = threadIdx.x >> 5;
    int gw = blockIdx.x * 8 + wid;
    int nw = gridDim.x * 8;
    float ba = bm1[lane], bb = bm1[lane + 32];
    float s0 = 0.f, q0 = 0.f, s1 = 0.f, q1 = 0.f;
    for (int e = gw; e < E; e += nw) {
        int s = ei[e];
        int d = ei[(size_t)E + e];
        float z = A[(size_t)s * 64 + lane] + B[(size_t)d * 64 + lane] + ba;
        z = fmaxf(z, 0.f);
        float w = A[(size_t)s * 64 + lane + 32] + B[(size_t)d * 64 + lane + 32] + bb;
        w = fmaxf(w, 0.f);
        s0 += z; q0 += z * z;
        s1 += w; q1 += w * w;
    }
    __shared__ float sh[8][64];
    sh[wid][lane] = s0; sh[wid][lane + 32] = s1;
    __syncthreads();
    if (threadIdx.x < 64) {
        float t = 0.f;
        for (int w = 0; w < 8; w++) t += sh[w][threadIdx.x];
        atomicAdd(&g_s1[threadIdx.x], (double)t);
    }
    __syncthreads();
    sh[wid][lane] = q0; sh[wid][lane + 32] = q1;
    __syncthreads();
    if (threadIdx.x < 64) {
        float t = 0.f;
        for (int w = 0; w < 8; w++) t += sh[w][threadIdx.x];
        atomicAdd(&g_q1[threadIdx.x], (double)t);
    }
}

// ---------------- fold BN1 into Wm2 -----------------------------------------
__global__ void fold1_kernel(const float* __restrict__ Wm2,
                             const float* __restrict__ bm2,
                             const float* __restrict__ g1,
                             const float* __restrict__ be1, double inv)
{
    int m = threadIdx.x;  // 32
    float bacc = bm2[m];
    for (int j = 0; j < 64; j++) {
        double mu = g_s1[j] * inv;
        double var = g_q1[j] * inv - mu * mu;
        float s = g1[j] * rsqrtf((float)var + 1e-5f);
        float t = be1[j] - (float)mu * s;
        float w = Wm2[j * 32 + m];
        g_W2f[j * 32 + m] = s * w;
        bacc += t * w;
    }
    g_b2f[m] = bacc;
}

// ---- edge pass 2 (tiled, f32x2): z2 = relu(z1 @ W2f + b2f); fused BN2 stats
// z1 staged PRE-DOUBLED: Zs_d[row][k] = {z, z} (ulonglong), row stride 66.
__global__ __launch_bounds__(256) void edge_pass2_kernel(
    const int* __restrict__ ei, const float* __restrict__ A,
    const float* __restrict__ B, const float* __restrict__ bm1, int E)
{
    __shared__ unsigned long long Zs_d[64][66];   // 33.8 KB, doubled z1 tile
    __shared__ float Ws[64 * 32];
    __shared__ float bs[64];
    __shared__ float b2s[32];
    __shared__ float blk_s[32], blk_q[32];
    __shared__ int   se[64], de[64];

    int tid = threadIdx.x;
    int lane = tid & 31;
    int wid = tid >> 5;
    if (tid < 64) bs[tid] = bm1[tid];
    if (tid < 32) { b2s[tid] = g_b2f[tid]; blk_s[tid] = 0.f; blk_q[tid] = 0.f; }
    for (int i = tid; i < 2048; i += 256) Ws[i] = g_W2f[i];
    __syncthreads();

    int r0 = (tid >> 3) * 2;        // rows r0, r0+1 (r0 even)
    int cg = (tid & 7) * 4;         // cols cg..cg+3

    float st_s[4] = {0.f, 0.f, 0.f, 0.f};
    float st_q[4] = {0.f, 0.f, 0.f, 0.f};

    int ntiles = (E + 63) >> 6;
    for (int tile = blockIdx.x; tile < ntiles; tile += gridDim.x) {
        int e0 = tile << 6;
        int ecount = min(64, E - e0);
        if (tid < ecount) {
            se[tid] = ei[e0 + tid];
            de[tid] = ei[(size_t)E + e0 + tid];
        }
        __syncthreads();

        // stage z1 doubled: warp w -> rows w*8..w*8+7; lane covers feats 2l,2l+1
        int rbase = wid * 8;
#pragma unroll
        for (int rr = 0; rr < 8; rr++) {
            int r = rbase + rr;
            float z0 = 0.f, z1 = 0.f;
            if (r < ecount) {
                int s = se[r], d = de[r];
                float2 a = ((const float2*)&A[(size_t)s * 64])[lane];
                float2 b = ((const float2*)&B[(size_t)d * 64])[lane];
                z0 = fmaxf(a.x + b.x + bs[2 * lane], 0.f);
                z1 = fmaxf(a.y + b.y + bs[2 * lane + 1], 0.f);
            }
            *(float4*)&Zs_d[r][2 * lane] = make_float4(z0, z0, z1, z1);
        }
        __syncthreads();

        // GEMM: 2 rows x 4 cols per thread, packed f32x2 accumulators
        unsigned long long a00 = *(const unsigned long long*)&b2s[cg];
        unsigned long long a01 = *(const unsigned long long*)&b2s[cg + 2];
        unsigned long long a10 = a00, a11 = a01;
#pragma unroll
        for (int k = 0; k < 64; k += 2) {
            ulonglong2 zz0 = *(const ulonglong2*)&Zs_d[r0][k];      // {z_k,z_k},{z_k1,z_k1}
            ulonglong2 zz1 = *(const ulonglong2*)&Zs_d[r0 + 1][k];
            ulonglong2 wk0 = *(const ulonglong2*)&Ws[k * 32 + cg];       // pairs (cg,cg+1),(cg+2,cg+3)
            ulonglong2 wk1 = *(const ulonglong2*)&Ws[(k + 1) * 32 + cg];
            asm("fma.rn.f32x2 %0, %1, %2, %0;" : "+l"(a00) : "l"(zz0.x), "l"(wk0.x));
            asm("fma.rn.f32x2 %0, %1, %2, %0;" : "+l"(a01) : "l"(zz0.x), "l"(wk0.y));
            asm("fma.rn.f32x2 %0, %1, %2, %0;" : "+l"(a10) : "l"(zz1.x), "l"(wk0.x));
            asm("fma.rn.f32x2 %0, %1, %2, %0;" : "+l"(a11) : "l"(zz1.x), "l"(wk0.y));
            asm("fma.rn.f32x2 %0, %1, %2, %0;" : "+l"(a00) : "l"(zz0.y), "l"(wk1.x));
            asm("fma.rn.f32x2 %0, %1, %2, %0;" : "+l"(a01) : "l"(zz0.y), "l"(wk1.y));
            asm("fma.rn.f32x2 %0, %1, %2, %0;" : "+l"(a10) : "l"(zz1.y), "l"(wk1.x));
            asm("fma.rn.f32x2 %0, %1, %2, %0;" : "+l"(a11) : "l"(zz1.y), "l"(wk1.y));
        }

        union { unsigned long long u; float f[2]; } u00, u01, u10, u11;
        u00.u = a00; u01.u = a01; u10.u = a10; u11.u = a11;
        float o0[4] = { fmaxf(u00.f[0], 0.f), fmaxf(u00.f[1], 0.f),
                        fmaxf(u01.f[0], 0.f), fmaxf(u01.f[1], 0.f) };
        float o1[4] = { fmaxf(u10.f[0], 0.f), fmaxf(u10.f[1], 0.f),
                        fmaxf(u11.f[0], 0.f), fmaxf(u11.f[1], 0.f) };

        if (e0 + r0 < E) {
            *(float4*)&g_z2[(size_t)(e0 + r0) * 32 + cg] = *(float4*)o0;
#pragma unroll
            for (int j = 0; j < 4; j++) { st_s[j] += o0[j]; st_q[j] += o0[j] * o0[j]; }
        }
        if (e0 + r0 + 1 < E) {
            *(float4*)&g_z2[(size_t)(e0 + r0 + 1) * 32 + cg] = *(float4*)o1;
#pragma unroll
            for (int j = 0; j < 4; j++) { st_s[j] += o1[j]; st_q[j] += o1[j] * o1[j]; }
        }
        __syncthreads();   // before next tile overwrites se/de/Zs_d
    }

    // flush per-block stats
#pragma unroll
    for (int j = 0; j < 4; j++) {
        atomicAdd(&blk_s[cg + j], st_s[j]);
        atomicAdd(&blk_q[cg + j], st_q[j]);
    }
    __syncthreads();
    if (tid < 32) {
        atomicAdd(&g_s2[tid], (double)blk_s[tid]);
        atomicAdd(&g_q2[tid], (double)blk_q[tid]);
    }
}

// ---------------- fold BN2 into Wm3 -----------------------------------------
__global__ void fold2_kernel(const float* __restrict__ Wm3,
                             const float* __restrict__ bm3,
                             const float* __restrict__ g2,
                             const float* __restrict__ be2, double inv)
{
    int k = threadIdx.x;
    if (k >= 2) return;
    float bacc = bm3[k];
    for (int m = 0; m < 32; m++) {
        double mu = g_s2[m] * inv;
        double var = g_q2[m] * inv - mu * mu;
        float s = g2[m] * rsqrtf((float)var + 1e-5f);
        float t = be2[m] - (float)mu * s;
        float w = Wm3[m * 2 + k];
        g_W3f[m * 2 + k] = s * w;
        bacc += t * w;
    }
    g_b3f[k] = bacc;
}

// ---------------- edge pass 3: out = z2 @ W3f + b3f -------------------------
__global__ __launch_bounds__(256) void edge_pass3_kernel(float* __restrict__ out, int E) {
    __shared__ float W0[32], W1s[32];
    __shared__ float bb[2];
    int tid = threadIdx.x;
    if (tid < 32) { W0[tid] = g_W3f[tid * 2]; W1s[tid] = g_W3f[tid * 2 + 1]; }
    if (tid < 2) bb[tid] = g_b3f[tid];
    __syncthreads();
    int stride = gridDim.x * 256;
    for (int e = blockIdx.x * 256 + tid; e < E; e += stride) {
        const float4* z4 = (const float4*)&g_z2[(size_t)e * 32];
        float o0 = bb[0], o1 = bb[1];
#pragma unroll
        for (int m4 = 0; m4 < 8; m4++) {
            float4 z = z4[m4];
            o0 += z.x * W0[m4 * 4 + 0] + z.y * W0[m4 * 4 + 1] +
                  z.z * W0[m4 * 4 + 2] + z.w * W0[m4 * 4 + 3];
            o1 += z.x * W1s[m4 * 4 + 0] + z.y * W1s[m4 * 4 + 1] +
                  z.z * W1s[m4 * 4 + 2] + z.w * W1s[m4 * 4 + 3];
        }
        *(float2*)&out[(size_t)e * 2] = make_float2(o0, o1);
    }
}

// ---------------- host launcher ---------------------------------------------
extern "C" void kernel_launch(void* const* d_in, const int* in_sizes, int n_in,
                              void* d_out, int out_size)
{
    const float* x = (const float*)d_in[0];
    const int* ei = (const int*)d_in[1];
    const float* W1 = (const float*)d_in[2];
    const float* b1 = (const float*)d_in[3];
    const float* W2 = (const float*)d_in[4];
    const float* b2 = (const float*)d_in[5];
    const float* W3 = (const float*)d_in[6];
    const float* b3 = (const float*)d_in[7];
    const float* Wm1 = (const float*)d_in[8];
    const float* bm1 = (const float*)d_in[9];
    const float* g1 = (const float*)d_in[10];
    const float* be1 = (const float*)d_in[11];
    const float* Wm2 = (const float*)d_in[12];
    const float* bm2 = (const float*)d_in[13];
    const float* g2 = (const float*)d_in[14];
    const float* be2 = (const float*)d_in[15];
    const float* Wm3 = (const float*)d_in[16];
    const float* bm3 = (const float*)d_in[17];

    int n = in_sizes[0] / 3;
    int E = in_sizes[1] / 2;

    float *B0, *B1p, *B2;
    cudaGetSymbolAddress((void**)&B0, g_B0);
    cudaGetSymbolAddress((void**)&B1p, g_B1);
    cudaGetSymbolAddress((void**)&B2, g_B2);

    int nb_node = (n + 255) / 256;
    int nb_edge = (E + 255) / 256;
    int nb_node16 = (n * 16 + 255) / 256;
    int nb_edge16 = (int)(((long long)E * 16 + 255) / 256);
    int nb_gemm = (n + 63) / 64;

    // degree (+ stats zero fused)
    deg_init_kernel<<<nb_node, 256>>>(n);
    deg_count_kernel<<<nb_edge, 256>>>(ei, E);
    deg_finish_kernel<<<nb_node, 256>>>(n);

    // layer 1: B0 = x@W1 ; B1 = b1 + B0*dinv^2 (fused) ; scatter into B1
    gemm_k3_kernel<<<nb_node16, 256>>>(x, W1, b1, B0, B1p, n);   // profiled (#4)
    scatter_kernel<<<nb_edge16, 256>>>(ei, B0, B1p, E);

    // layer 2: B0 = relu(B1)@W2 ; B2 = b2 + B0*dinv^2 (fused) ; scatter into B2
    gemm64_kernel<<<nb_gemm, 256>>>(B1p, W2, B0, b2, B2, n, 1);
    scatter_kernel<<<nb_edge16, 256>>>(ei, B0, B2, E);

    // layer 3: B0 = relu(B2)@W3 ; B1 = b3 + B0*dinv^2 (fused) ; scatter into B1 (= h3)
    gemm64_kernel<<<nb_gemm, 256>>>(B2, W3, B0, b3, B1p, n, 1);
    scatter_kernel<<<nb_edge16, 256>>>(ei, B0, B1p, E);

    // projections: a = h3@Wm1_top -> B0 ; b = h3@Wm1_bot -> B2
    gemm64_kernel<<<nb_gemm, 256>>>(B1p, Wm1, B0, (const float*)0, (float*)0, n, 0);
    gemm64_kernel<<<nb_gemm, 256>>>(B1p, Wm1 + 64 * 64, B2, (const float*)0, (float*)0, n, 0);

    // edge MLP (stats2 fused into pass2)
    edge_pass1_kernel<<<1024, 256>>>(ei, B0, B2, bm1, E);
    fold1_kernel<<<1, 32>>>(Wm2, bm2, g1, be1, 1.0 / (double)E);
    edge_pass2_kernel<<<2048, 256>>>(ei, B0, B2, bm1, E);
    fold2_kernel<<<1, 32>>>(Wm3, bm3, g2, be2, 1.0 / (double)E);
    edge_pass3_kernel<<<2048, 256>>>((float*)d_out, E);
}

// round 12
// speedup vs baseline: 1.0488x; 1.0488x over previous
#include <cuda_runtime.h>
#include <cstdint>

#define NN 100000
#define EE 1600000
#define HID 64

// ---------------- device scratch (no runtime allocation allowed) ------------
__device__ float g_B0[NN * HID];
__device__ float g_B1[NN * HID];
__device__ float g_B2[NN * HID];
__device__ float g_dinv[NN];
__device__ float g_deg[NN];
__device__ float g_z2[(size_t)EE * (HID / 2)];
__device__ double g_s1[HID], g_q1[HID];
__device__ double g_s2[HID / 2], g_q2[HID / 2];
__device__ float g_W2f[HID * (HID / 2)];
__device__ float g_b2f[HID / 2];
__device__ float g_W3f[(HID / 2) * 2];
__device__ float g_b3f[2];

// ---------------- degree + stats init ---------------------------------------
__global__ void deg_init_kernel(int n) {
    int v = blockIdx.x * 256 + threadIdx.x;
    if (v < n) g_deg[v] = 1.0f;  // self-loop
    if (blockIdx.x == 0) {
        int t = threadIdx.x;
        if (t < HID) { g_s1[t] = 0.0; g_q1[t] = 0.0; }
        if (t < HID / 2) { g_s2[t] = 0.0; g_q2[t] = 0.0; }
    }
}

__global__ void deg_count_kernel(const int* __restrict__ ei, int E) {
    int e = blockIdx.x * 256 + threadIdx.x;
    if (e < E) atomicAdd(&g_deg[ei[(size_t)E + e]], 1.0f);
}

__global__ void deg_finish_kernel(int n) {
    int v = blockIdx.x * 256 + threadIdx.x;
    if (v < n) g_dinv[v] = rsqrtf(g_deg[v]);
}

// ---------------- layer-1 GEMM (K=3) + fused self-init ----------------------
// C = x@W1 ; O = b1 + C*dinv^2   (O is the scatter accumulator base)
__global__ __launch_bounds__(256) void gemm_k3_kernel(
    const float* __restrict__ X, const float* __restrict__ W,
    const float* __restrict__ bias,
    float* __restrict__ C, float* __restrict__ O, int n)
{
    __shared__ float Ws[3 * 64];
    int tid = threadIdx.x;
    if (tid < 192) Ws[tid] = W[tid];
    __syncthreads();
    int idx = blockIdx.x * 256 + tid;
    int v = idx >> 4;
    int c4 = (idx & 15) * 4;
    if (v >= n) return;
    float x0 = X[v * 3 + 0], x1 = X[v * 3 + 1], x2 = X[v * 3 + 2];
    float4 w0 = *(const float4*)&Ws[0 * 64 + c4];
    float4 w1 = *(const float4*)&Ws[1 * 64 + c4];
    float4 w2 = *(const float4*)&Ws[2 * 64 + c4];
    float4 o;
    o.x = x0 * w0.x + x1 * w1.x + x2 * w2.x;
    o.y = x0 * w0.y + x1 * w1.y + x2 * w2.y;
    o.z = x0 * w0.z + x1 * w1.z + x2 * w2.z;
    o.w = x0 * w0.w + x1 * w1.w + x2 * w2.w;
    *(float4*)&C[v * 64 + c4] = o;
    float dv = g_dinv[v];
    float sw = dv * dv;
    float4 b4 = *(const float4*)&bias[c4];
    float4 s;
    s.x = b4.x + o.x * sw; s.y = b4.y + o.y * sw;
    s.z = b4.z + o.z * sw; s.w = b4.w + o.w * sw;
    *(float4*)&O[(size_t)v * 64 + c4] = s;
}

// ---------------- 64x64 tiled GEMM + optional fused self-init ---------------
// C = [relu](A) @ W ; if O != null:  O = bias_self + C*dinv^2
__global__ __launch_bounds__(256) void gemm64_kernel(
    const float* __restrict__ A, const float* __restrict__ W,
    float* __restrict__ C, const float* __restrict__ bias_self,
    float* __restrict__ O, int n, int relu_in)
{
    __shared__ float As[64 * 68];
    __shared__ float Ws[64 * 64];
    int tid = threadIdx.x;
    int rowbase = blockIdx.x * 64;

    for (int i = tid; i < 1024; i += 256)
        ((float4*)Ws)[i] = ((const float4*)W)[i];

    for (int i = tid; i < 1024; i += 256) {
        int r = i >> 4;
        int c4 = (i & 15) * 4;
        float4 v;
        if (rowbase + r < n) v = *(const float4*)&A[(size_t)(rowbase + r) * 64 + c4];
        else v = make_float4(0.f, 0.f, 0.f, 0.f);
        if (relu_in) {
            v.x = fmaxf(v.x, 0.f); v.y = fmaxf(v.y, 0.f);
            v.z = fmaxf(v.z, 0.f); v.w = fmaxf(v.w, 0.f);
        }
        *(float4*)&As[r * 68 + c4] = v;
    }
    __syncthreads();

    int rg = (tid >> 4) * 4;
    int cg = (tid & 15) * 4;
    float4 acc0 = make_float4(0, 0, 0, 0), acc1 = acc0, acc2 = acc0, acc3 = acc0;
#pragma unroll
    for (int k = 0; k < 64; k++) {
        float4 wv = *(const float4*)&Ws[k * 64 + cg];
        float a0 = As[(rg + 0) * 68 + k];
        float a1 = As[(rg + 1) * 68 + k];
        float a2 = As[(rg + 2) * 68 + k];
        float a3 = As[(rg + 3) * 68 + k];
        acc0.x += a0 * wv.x; acc0.y += a0 * wv.y; acc0.z += a0 * wv.z; acc0.w += a0 * wv.w;
        acc1.x += a1 * wv.x; acc1.y += a1 * wv.y; acc1.z += a1 * wv.z; acc1.w += a1 * wv.w;
        acc2.x += a2 * wv.x; acc2.y += a2 * wv.y; acc2.z += a2 * wv.z; acc2.w += a2 * wv.w;
        acc3.x += a3 * wv.x; acc3.y += a3 * wv.y; acc3.z += a3 * wv.z; acc3.w += a3 * wv.w;
    }
    float4 accs[4] = {acc0, acc1, acc2, acc3};
#pragma unroll
    for (int rr = 0; rr < 4; rr++) {
        int row = rowbase + rg + rr;
        if (row < n) {
            *(float4*)&C[(size_t)row * 64 + cg] = accs[rr];
            if (O) {
                float dv = g_dinv[row];
                float sw = dv * dv;
                float4 b4 = *(const float4*)&bias_self[cg];
                float4 s;
                s.x = b4.x + accs[rr].x * sw; s.y = b4.y + accs[rr].y * sw;
                s.z = b4.z + accs[rr].z * sw; s.w = b4.w + accs[rr].w * sw;
                *(float4*)&O[(size_t)row * 64 + cg] = s;
            }
        }
    }
}

// ---------------- edge scatter: O[col] += T[row] * dinv[row]*dinv[col] -------
__global__ __launch_bounds__(256) void scatter_kernel(
    const int* __restrict__ ei, const float* __restrict__ T,
    float* __restrict__ O, int E)
{
    long long idx = (long long)blockIdx.x * 256 + threadIdx.x;
    int e = (int)(idx >> 4);
    int part = ((int)idx & 15) * 4;
    if (e >= E) return;
    int r = ei[e];
    int c = ei[(size_t)E + e];
    float w = g_dinv[r] * g_dinv[c];
    float4 v = *(const float4*)&T[(size_t)r * 64 + part];
    v.x *= w; v.y *= w; v.z *= w; v.w *= w;
    float* p = &O[(size_t)c * 64 + part];
    asm volatile("red.global.add.v4.f32 [%0], {%1,%2,%3,%4};"
                 :: "l"(p), "f"(v.x), "f"(v.y), "f"(v.z), "f"(v.w) : "memory");
}

// ---------------- edge pass 1: BN1 statistics of z1 -------------------------
__global__ __launch_bounds__(256) void edge_pass1_kernel(
    const int* __restrict__ ei, const float* __restrict__ A,
    const float* __restrict__ B, const float* __restrict__ bm1, int E)
{
    int lane = threadIdx.x & 31;
    int wid = threadIdx.x >> 5;
    int gw = blockIdx.x * 8 + wid;
    int nw = gridDim.x * 8;
    float ba = bm1[lane], bb = bm1[lane + 32];
    float s0 = 0.f, q0 = 0.f, s1 = 0.f, q1 = 0.f;
    for (int e = gw; e < E; e += nw) {
        int s = ei[e];
        int d = ei[(size_t)E + e];
        float z = A[(size_t)s * 64 + lane] + B[(size_t)d * 64 + lane] + ba;
        z = fmaxf(z, 0.f);
        float w = A[(size_t)s * 64 + lane + 32] + B[(size_t)d * 64 + lane + 32] + bb;
        w = fmaxf(w, 0.f);
        s0 += z; q0 += z * z;
        s1 += w; q1 += w * w;
    }
    __shared__ float sh[8][64];
    sh[wid][lane] = s0; sh[wid][lane + 32] = s1;
    __syncthreads();
    if (threadIdx.x < 64) {
        float t = 0.f;
        for (int w = 0; w < 8; w++) t += sh[w][threadIdx.x];
        atomicAdd(&g_s1[threadIdx.x], (double)t);
    }
    __syncthreads();
    sh[wid][lane] = q0; sh[wid][lane + 32] = q1;
    __syncthreads();
    if (threadIdx.x < 64) {
        float t = 0.f;
        for (int w = 0; w < 8; w++) t += sh[w][threadIdx.x];
        atomicAdd(&g_q1[threadIdx.x], (double)t);
    }
}

// ---------------- fold BN1 into Wm2 -----------------------------------------
__global__ void fold1_kernel(const float* __restrict__ Wm2,
                             const float* __restrict__ bm2,
                             const float* __restrict__ g1,
                             const float* __restrict__ be1, double inv)
{
    int m = threadIdx.x;  // 32
    float bacc = bm2[m];
    for (int j = 0; j < 64; j++) {
        double mu = g_s1[j] * inv;
        double var = g_q1[j] * inv - mu * mu;
        float s = g1[j] * rsqrtf((float)var + 1e-5f);
        float t = be1[j] - (float)mu * s;
        float w = Wm2[j * 32 + m];
        g_W2f[j * 32 + m] = s * w;
        bacc += t * w;
    }
    g_b2f[m] = bacc;
}

// ---- edge pass 2 (tiled): z2 = relu(z1 @ W2f + b2f); fused BN2 stats -------
// Block handles tiles of 64 edges. Smem-staged z1, register-blocked GEMM.
__global__ __launch_bounds__(256) void edge_pass2_kernel(
    const int* __restrict__ ei, const float* __restrict__ A,
    const float* __restrict__ B, const float* __restrict__ bm1, int E)
{
    __shared__ float Zs[64][68];     // z1 tile (pad 68 -> 272B rows, 16B aligned)
    __shared__ float Ws[64 * 32];
    __shared__ float bs[64];
    __shared__ float b2s[32];
    __shared__ float blk_s[32], blk_q[32];
    __shared__ int   se[64], de[64];

    int tid = threadIdx.x;
    int lane = tid & 31;
    int wid = tid >> 5;
    if (tid < 64) bs[tid] = bm1[tid];
    if (tid < 32) { b2s[tid] = g_b2f[tid]; blk_s[tid] = 0.f; blk_q[tid] = 0.f; }
    for (int i = tid; i < 2048; i += 256) Ws[i] = g_W2f[i];
    __syncthreads();

    int r0 = (tid >> 3) * 2;        // rows r0, r0+1
    int cg = (tid & 7) * 4;         // cols cg..cg+3

    float st_s[4] = {0.f, 0.f, 0.f, 0.f};
    float st_q[4] = {0.f, 0.f, 0.f, 0.f};

    int ntiles = (E + 63) >> 6;
    for (int tile = blockIdx.x; tile < ntiles; tile += gridDim.x) {
        int e0 = tile << 6;
        int ecount = min(64, E - e0);
        if (tid < ecount) {
            se[tid] = ei[e0 + tid];
            de[tid] = ei[(size_t)E + e0 + tid];
        }
        __syncthreads();

        // stage z1: warp w -> rows w*8 .. w*8+7, coalesced float2 per lane
        int rbase = wid * 8;
#pragma unroll
        for (int rr = 0; rr < 8; rr++) {
            int r = rbase + rr;
            float z0 = 0.f, z1 = 0.f;
            if (r < ecount) {
                int s = se[r], d = de[r];
                float2 a = ((const float2*)&A[(size_t)s * 64])[lane];
                float2 b = ((const float2*)&B[(size_t)d * 64])[lane];
                z0 = fmaxf(a.x + b.x + bs[2 * lane], 0.f);
                z1 = fmaxf(a.y + b.y + bs[2 * lane + 1], 0.f);
            }
            Zs[r][2 * lane] = z0;
            Zs[r][2 * lane + 1] = z1;
        }
        __syncthreads();

        // GEMM: 2 rows x 4 cols per thread over k=64
        float acc0[4], acc1[4];
#pragma unroll
        for (int j = 0; j < 4; j++) { acc0[j] = b2s[cg + j]; acc1[j] = b2s[cg + j]; }
#pragma unroll
        for (int k = 0; k < 64; k += 4) {
            float a0r[4], a1r[4];
            *(float4*)a0r = *(const float4*)&Zs[r0][k];
            *(float4*)a1r = *(const float4*)&Zs[r0 + 1][k];
#pragma unroll
            for (int kk = 0; kk < 4; kk++) {
                float wr[4];
                *(float4*)wr = *(const float4*)&Ws[(k + kk) * 32 + cg];
#pragma unroll
                for (int j = 0; j < 4; j++) {
                    acc0[j] += a0r[kk] * wr[j];
                    acc1[j] += a1r[kk] * wr[j];
                }
            }
        }

        bool v0 = (e0 + r0) < E;
        bool v1 = (e0 + r0 + 1) < E;
        float o0[4], o1[4];
#pragma unroll
        for (int j = 0; j < 4; j++) {
            o0[j] = fmaxf(acc0[j], 0.f);
            o1[j] = fmaxf(acc1[j], 0.f);
        }
        if (v0) {
            *(float4*)&g_z2[(size_t)(e0 + r0) * 32 + cg] = *(float4*)o0;
#pragma unroll
            for (int j = 0; j < 4; j++) { st_s[j] += o0[j]; st_q[j] += o0[j] * o0[j]; }
        }
        if (v1) {
            *(float4*)&g_z2[(size_t)(e0 + r0 + 1) * 32 + cg] = *(float4*)o1;
#pragma unroll
            for (int j = 0; j < 4; j++) { st_s[j] += o1[j]; st_q[j] += o1[j] * o1[j]; }
        }
        __syncthreads();   // before next tile overwrites se/de/Zs
    }

    // flush per-block stats
#pragma unroll
    for (int j = 0; j < 4; j++) {
        atomicAdd(&blk_s[cg + j], st_s[j]);
        atomicAdd(&blk_q[cg + j], st_q[j]);
    }
    __syncthreads();
    if (tid < 32) {
        atomicAdd(&g_s2[tid], (double)blk_s[tid]);
        atomicAdd(&g_q2[tid], (double)blk_q[tid]);
    }
}

// ---------------- fold BN2 into Wm3 -----------------------------------------
__global__ void fold2_kernel(const float* __restrict__ Wm3,
                             const float* __restrict__ bm3,
                             const float* __restrict__ g2,
                             const float* __restrict__ be2, double inv)
{
    int k = threadIdx.x;
    if (k >= 2) return;
    float bacc = bm3[k];
    for (int m = 0; m < 32; m++) {
        double mu = g_s2[m] * inv;
        double var = g_q2[m] * inv - mu * mu;
        float s = g2[m] * rsqrtf((float)var + 1e-5f);
        float t = be2[m] - (float)mu * s;
        float w = Wm3[m * 2 + k];
        g_W3f[m * 2 + k] = s * w;
        bacc += t * w;
    }
    g_b3f[k] = bacc;
}

// ---------------- edge pass 3: out = z2 @ W3f + b3f -------------------------
__global__ __launch_bounds__(256) void edge_pass3_kernel(float* __restrict__ out, int E) {
    __shared__ float W0[32], W1s[32];
    __shared__ float bb[2];
    int tid = threadIdx.x;
    if (tid < 32) { W0[tid] = g_W3f[tid * 2]; W1s[tid] = g_W3f[tid * 2 + 1]; }
    if (tid < 2) bb[tid] = g_b3f[tid];
    __syncthreads();
    int stride = gridDim.x * 256;
    for (int e = blockIdx.x * 256 + tid; e < E; e += stride) {
        const float4* z4 = (const float4*)&g_z2[(size_t)e * 32];
        float o0 = bb[0], o1 = bb[1];
#pragma unroll
        for (int m4 = 0; m4 < 8; m4++) {
            float4 z = z4[m4];
            o0 += z.x * W0[m4 * 4 + 0] + z.y * W0[m4 * 4 + 1] +
                  z.z * W0[m4 * 4 + 2] + z.w * W0[m4 * 4 + 3];
            o1 += z.x * W1s[m4 * 4 + 0] + z.y * W1s[m4 * 4 + 1] +
                  z.z * W1s[m4 * 4 + 2] + z.w * W1s[m4 * 4 + 3];
        }
        *(float2*)&out[(size_t)e * 2] = make_float2(o0, o1);
    }
}

// ---------------- host launcher ---------------------------------------------
extern "C" void kernel_launch(void* const* d_in, const int* in_sizes, int n_in,
                              void* d_out, int out_size)
{
    const float* x = (const float*)d_in[0];
    const int* ei = (const int*)d_in[1];
    const float* W1 = (const float*)d_in[2];
    const float* b1 = (const float*)d_in[3];
    const float* W2 = (const float*)d_in[4];
    const float* b2 = (const float*)d_in[5];
    const float* W3 = (const float*)d_in[6];
    const float* b3 = (const float*)d_in[7];
    const float* Wm1 = (const float*)d_in[8];
    const float* bm1 = (const float*)d_in[9];
    const float* g1 = (const float*)d_in[10];
    const float* be1 = (const float*)d_in[11];
    const float* Wm2 = (const float*)d_in[12];
    const float* bm2 = (const float*)d_in[13];
    const float* g2 = (const float*)d_in[14];
    const float* be2 = (const float*)d_in[15];
    const float* Wm3 = (const float*)d_in[16];
    const float* bm3 = (const float*)d_in[17];

    int n = in_sizes[0] / 3;
    int E = in_sizes[1] / 2;

    float *B0, *B1p, *B2;
    cudaGetSymbolAddress((void**)&B0, g_B0);
    cudaGetSymbolAddress((void**)&B1p, g_B1);
    cudaGetSymbolAddress((void**)&B2, g_B2);

    int nb_node = (n + 255) / 256;
    int nb_edge = (E + 255) / 256;
    int nb_node16 = (n * 16 + 255) / 256;
    int nb_edge16 = (int)(((long long)E * 16 + 255) / 256);
    int nb_gemm = (n + 63) / 64;

    // degree (+ stats zero fused)
    deg_init_kernel<<<nb_node, 256>>>(n);
    deg_count_kernel<<<nb_edge, 256>>>(ei, E);
    deg_finish_kernel<<<nb_node, 256>>>(n);

    // layer 1: B0 = x@W1 ; B1 = b1 + B0*dinv^2 (fused) ; scatter into B1
    gemm_k3_kernel<<<nb_node16, 256>>>(x, W1, b1, B0, B1p, n);
    scatter_kernel<<<nb_edge16, 256>>>(ei, B0, B1p, E);

    // layer 2: B0 = relu(B1)@W2 ; B2 = b2 + B0*dinv^2 (fused) ; scatter into B2
    gemm64_kernel<<<nb_gemm, 256>>>(B1p, W2, B0, b2, B2, n, 1);
    scatter_kernel<<<nb_edge16, 256>>>(ei, B0, B2, E);

    // layer 3: B0 = relu(B2)@W3 ; B1 = b3 + B0*dinv^2 (fused) ; scatter into B1 (= h3)
    gemm64_kernel<<<nb_gemm, 256>>>(B2, W3, B0, b3, B1p, n, 1);
    scatter_kernel<<<nb_edge16, 256>>>(ei, B0, B1p, E);

    // projections: a = h3@Wm1_top -> B0 ; b = h3@Wm1_bot -> B2
    gemm64_kernel<<<nb_gemm, 256>>>(B1p, Wm1, B0, (const float*)0, (float*)0, n, 0);
    gemm64_kernel<<<nb_gemm, 256>>>(B1p, Wm1 + 64 * 64, B2, (const float*)0, (float*)0, n, 0);

    // edge MLP (stats2 fused into pass2)
    edge_pass1_kernel<<<1024, 256>>>(ei, B0, B2, bm1, E);
    fold1_kernel<<<1, 32>>>(Wm2, bm2, g1, be1, 1.0 / (double)E);
    edge_pass2_kernel<<<2048, 256>>>(ei, B0, B2, bm1, E);
    fold2_kernel<<<1, 32>>>(Wm3, bm3, g2, be2, 1.0 / (double)E);
    edge_pass3_kernel<<<2048, 256>>>((float*)d_out, E);
}